// round 1
// baseline (speedup 1.0000x reference)
#include <cuda_runtime.h>
#include <cstdint>

#define NBUS   4096
#define BATCH  64
#define MROWS  128        // 2*BATCH RHS rows
#define KDIM   8192       // 2*NBUS
#define BN     128
#define BK     32
#define KSPLIT 4
#define KLEN   (KDIM / KSPLIT)   // 2048
#define NKT    (KLEN / BK)       // 64
#define THREADS 256

// Scratch (no runtime allocation allowed)
__device__ float g_X[MROWS * KDIM];            // 4 MB: stacked RHS [c,s] / [s,-c]
__device__ float g_C[KSPLIT * MROWS * NBUS];   // 8 MB: K-split partials

// ---------------------------------------------------------------------------
// Kernel 1: build X
// row b      : [ c_b , s_b ]
// row 64+b   : [ s_b , -c_b ]
// ---------------------------------------------------------------------------
__global__ void prep_kernel(const float* __restrict__ Vm,
                            const float* __restrict__ Va) {
    int idx = blockIdx.x * blockDim.x + threadIdx.x;
    if (idx >= BATCH * NBUS) return;
    int b = idx >> 12;
    int j = idx & (NBUS - 1);
    float vm = Vm[idx], va = Va[idx];
    float sn, cs;
    sincosf(va, &sn, &cs);
    float c = vm * cs;
    float s = vm * sn;
    g_X[b * KDIM + j]                    = c;
    g_X[b * KDIM + NBUS + j]             = s;
    g_X[(BATCH + b) * KDIM + j]          = s;
    g_X[(BATCH + b) * KDIM + NBUS + j]   = -c;
}

// ---------------------------------------------------------------------------
// tf32 helpers
// ---------------------------------------------------------------------------
__device__ __forceinline__ uint32_t cvt_tf32(float f) {
    uint32_t u;
    asm("cvt.rna.tf32.f32 %0, %1;" : "=r"(u) : "f"(f));
    return u;
}

// XOR swizzle inside a 128-byte (32-float) row: conflict-free mma frag loads
__device__ __forceinline__ int swz(int row, int col) {
    return row * BK + ((((col >> 2) ^ (row & 7)) << 2) | (col & 3));
}

__device__ __forceinline__ void cp16(uint32_t saddr, const float* gptr) {
    asm volatile("cp.async.cg.shared.global [%0], [%1], 16;\n"
                 :: "r"(saddr), "l"(gptr));
}

// ---------------------------------------------------------------------------
// Kernel 2: C[128,4096] = X[128,8192] @ [G|B]^T  (tf32 mma, K-split partials)
//   blockIdx.x : N tile (BN=128 bus columns), blockIdx.y : K split (2048 each)
// ---------------------------------------------------------------------------
__global__ void __launch_bounds__(THREADS)
gemm_kernel(const float* __restrict__ Gm, const float* __restrict__ Bm) {
    extern __shared__ float smem[];   // [2 stages][ X:128x32 | A:128x32 ]

    const int n0   = blockIdx.x * BN;
    const int ks   = blockIdx.y;
    const float* mat = (ks < 2) ? Gm : Bm;
    const int kmat0 = (ks & 1) * KLEN;   // column offset inside G or B
    const int kx0   = ks * KLEN;         // column offset inside X

    const int tid  = threadIdx.x;
    const int lane = tid & 31;
    const int warp = tid >> 5;
    const int wm   = warp & 1;    // 2 M-warps * 64 rows
    const int wn   = warp >> 1;   // 4 N-warps * 32 cols
    const int gid  = lane >> 2;
    const int tig  = lane & 3;

    uint32_t sbase;
    asm("{ .reg .u64 t; cvta.to.shared.u64 t, %1; cvt.u32.u64 %0, t; }"
        : "=r"(sbase) : "l"(smem));

    float acc[4][4][4];
#pragma unroll
    for (int mi = 0; mi < 4; ++mi)
#pragma unroll
        for (int ni = 0; ni < 4; ++ni)
#pragma unroll
            for (int q = 0; q < 4; ++q) acc[mi][ni][q] = 0.f;

    auto issue = [&](int stage, int kt) {
        const int kbx = kx0 + kt * BK;
        const int kbm = kmat0 + kt * BK;
        uint32_t sx = sbase + (uint32_t)stage * 8192u * 4u;
        uint32_t sa = sx + 4096u * 4u;
#pragma unroll
        for (int it = 0; it < 4; ++it) {
            int v = tid + it * 256;
            int row = v >> 3;          // 8 float4 per 32-float row
            int colv = v & 7;
            int scol = (colv ^ (row & 7)) << 2;
            cp16(sx + (uint32_t)(row * BK + scol) * 4u,
                 &g_X[row * KDIM + kbx + colv * 4]);
            cp16(sa + (uint32_t)(row * BK + scol) * 4u,
                 &mat[(size_t)(n0 + row) * NBUS + kbm + colv * 4]);
        }
    };

    issue(0, 0);
    asm volatile("cp.async.commit_group;");

    for (int kt = 0; kt < NKT; ++kt) {
        asm volatile("cp.async.wait_group 0;");
        __syncthreads();
        if (kt + 1 < NKT) {
            issue((kt + 1) & 1, kt + 1);
            asm volatile("cp.async.commit_group;");
        }

        const int st = kt & 1;
        const float* sX = smem + st * 8192;
        const float* sA = sX + 4096;

#pragma unroll
        for (int kk = 0; kk < 4; ++kk) {
            const int koff = kk * 8;

            uint32_t afr[4][4];
#pragma unroll
            for (int mi = 0; mi < 4; ++mi) {
                int r0 = wm * 64 + mi * 16 + gid;
                int c0 = koff + tig;
                afr[mi][0] = cvt_tf32(sX[swz(r0,     c0)]);
                afr[mi][1] = cvt_tf32(sX[swz(r0 + 8, c0)]);
                afr[mi][2] = cvt_tf32(sX[swz(r0,     c0 + 4)]);
                afr[mi][3] = cvt_tf32(sX[swz(r0 + 8, c0 + 4)]);
            }
            uint32_t bfr[4][2];
#pragma unroll
            for (int ni = 0; ni < 4; ++ni) {
                int n  = wn * 32 + ni * 8 + gid;
                int c0 = koff + tig;
                bfr[ni][0] = cvt_tf32(sA[swz(n, c0)]);
                bfr[ni][1] = cvt_tf32(sA[swz(n, c0 + 4)]);
            }
#pragma unroll
            for (int mi = 0; mi < 4; ++mi)
#pragma unroll
                for (int ni = 0; ni < 4; ++ni)
                    asm volatile(
                        "mma.sync.aligned.m16n8k8.row.col.f32.tf32.tf32.f32 "
                        "{%0,%1,%2,%3}, {%4,%5,%6,%7}, {%8,%9}, {%0,%1,%2,%3};"
                        : "+f"(acc[mi][ni][0]), "+f"(acc[mi][ni][1]),
                          "+f"(acc[mi][ni][2]), "+f"(acc[mi][ni][3])
                        : "r"(afr[mi][0]), "r"(afr[mi][1]),
                          "r"(afr[mi][2]), "r"(afr[mi][3]),
                          "r"(bfr[ni][0]), "r"(bfr[ni][1]));
        }
    }

    // write K-split partial
    float* outp = g_C + (size_t)ks * MROWS * NBUS;
#pragma unroll
    for (int mi = 0; mi < 4; ++mi) {
        int r0 = wm * 64 + mi * 16 + gid;
#pragma unroll
        for (int ni = 0; ni < 4; ++ni) {
            int col = n0 + wn * 32 + ni * 8 + tig * 2;
            *(float2*)&outp[(size_t)r0 * NBUS + col] =
                make_float2(acc[mi][ni][0], acc[mi][ni][1]);
            *(float2*)&outp[(size_t)(r0 + 8) * NBUS + col] =
                make_float2(acc[mi][ni][2], acc[mi][ni][3]);
        }
    }
}

// ---------------------------------------------------------------------------
// Kernel 3: reduce K-split partials + power-flow epilogue
// ---------------------------------------------------------------------------
__global__ void epilogue_kernel(const float* __restrict__ Vm,
                                const float* __restrict__ Va,
                                const float* __restrict__ Pin,
                                const float* __restrict__ Qin,
                                float* __restrict__ out) {
    int idx = blockIdx.x * blockDim.x + threadIdx.x;
    if (idx >= BATCH * NBUS) return;
    int b = idx >> 12;
    int i = idx & (NBUS - 1);
    float U = 0.f, W = 0.f;
#pragma unroll
    for (int ks = 0; ks < KSPLIT; ++ks) {
        U += g_C[((size_t)(ks * MROWS) + b) * NBUS + i];
        W += g_C[((size_t)(ks * MROWS) + BATCH + b) * NBUS + i];
    }
    float vm = Vm[idx];
    float sn, cs;
    sincosf(Va[idx], &sn, &cs);
    out[idx]                = vm * (cs * U + sn * W) - Pin[idx];   // res_P
    out[BATCH * NBUS + idx] = vm * (sn * U - cs * W) - Qin[idx];   // res_Q
}

// ---------------------------------------------------------------------------
extern "C" void kernel_launch(void* const* d_in, const int* in_sizes, int n_in,
                              void* d_out, int out_size) {
    const float* Vm  = (const float*)d_in[0];
    const float* Va  = (const float*)d_in[1];
    const float* Pin = (const float*)d_in[2];
    const float* Qin = (const float*)d_in[3];
    const float* Gm  = (const float*)d_in[4];
    const float* Bm  = (const float*)d_in[5];
    float* out = (float*)d_out;

    cudaFuncSetAttribute(gemm_kernel,
                         cudaFuncAttributeMaxDynamicSharedMemorySize, 65536);

    prep_kernel<<<(BATCH * NBUS + 255) / 256, 256>>>(Vm, Va);
    gemm_kernel<<<dim3(NBUS / BN, KSPLIT), THREADS, 65536>>>(Gm, Bm);
    epilogue_kernel<<<(BATCH * NBUS + 255) / 256, 256>>>(Vm, Va, Pin, Qin, out);
}

// round 3
// speedup vs baseline: 1.3966x; 1.3966x over previous
#include <cuda_runtime.h>
#include <cuda_fp16.h>
#include <cstdint>

#define NBUS   4096
#define BATCH  64
#define MROWS  128        // 2*BATCH RHS rows
#define KDIM   8192       // 2*NBUS
#define BN     128
#define BK     32         // K per tile
#define KSPLIT 4
#define KLEN   (KDIM / KSPLIT)   // 2048
#define NKT    (KLEN / BK)       // 64
#define NSTAGES 4
#define THREADS 256

#define HSTRIDE 40                 // halves per padded row (80 B, 20-bank stride)
#define STAGE_A   10240            // fp16 X tile 128 x 32 (padded rows)
#define STAGE_BF  16384            // fp32 B staging 128 x 32
#define STAGE_B16 10240            // fp16 B tile
#define STAGE_BYTES (STAGE_A + STAGE_BF + STAGE_B16)   // 36864
#define SMEM_TOTAL  (NSTAGES * STAGE_BYTES)            // 147456

// Scratch (no runtime allocation allowed)
__device__ __half g_X16[MROWS * KDIM];          // 2 MB stacked RHS (fp16)
__device__ float  g_C[KSPLIT * MROWS * NBUS];   // 8 MB K-split partials

// ---------------------------------------------------------------------------
// Kernel 1: build X (fp16), 4 elements per thread
// row b      : [ c_b , s_b ]      row 64+b : [ s_b , -c_b ]
// ---------------------------------------------------------------------------
__global__ void prep_kernel(const float* __restrict__ Vm,
                            const float* __restrict__ Va) {
    int t = blockIdx.x * blockDim.x + threadIdx.x;   // over BATCH*NBUS/4
    if (t >= BATCH * NBUS / 4) return;
    int e = t * 4;
    int b = e >> 12;
    int j = e & (NBUS - 1);
    const float4 vm = *(const float4*)&Vm[e];
    const float4 va = *(const float4*)&Va[e];
    float vmv[4] = {vm.x, vm.y, vm.z, vm.w};
    float vav[4] = {va.x, va.y, va.z, va.w};
    __half hc[4], hs[4], hn[4];
#pragma unroll
    for (int q = 0; q < 4; ++q) {
        float sn, cs;
        sincosf(vav[q], &sn, &cs);
        hc[q] = __float2half_rn(vmv[q] * cs);
        hs[q] = __float2half_rn(vmv[q] * sn);
        hn[q] = __hneg(hc[q]);
    }
    *(uint2*)&g_X16[b * KDIM + j]                  = *(uint2*)hc;
    *(uint2*)&g_X16[b * KDIM + NBUS + j]           = *(uint2*)hs;
    *(uint2*)&g_X16[(BATCH + b) * KDIM + j]        = *(uint2*)hs;
    *(uint2*)&g_X16[(BATCH + b) * KDIM + NBUS + j] = *(uint2*)hn;
}

// ---------------------------------------------------------------------------
__device__ __forceinline__ void cp16(uint32_t saddr, const void* gptr) {
    asm volatile("cp.async.cg.shared.global [%0], [%1], 16;\n"
                 :: "r"(saddr), "l"(gptr));
}

// ---------------------------------------------------------------------------
// fp16 GEMM: C[128,4096] = X[128,8192] @ [G|B]^T  (K-split partials)
// ---------------------------------------------------------------------------
__global__ void __launch_bounds__(THREADS)
gemm_kernel(const float* __restrict__ Gm, const float* __restrict__ Bm) {
    extern __shared__ char smem[];
    uint32_t sbase;
    asm("{ .reg .u64 t; cvta.to.shared.u64 t, %1; cvt.u32.u64 %0, t; }"
        : "=r"(sbase) : "l"(smem));

    const int tid  = threadIdx.x;
    const int lane = tid & 31;
    const int warp = tid >> 5;
    const int wm   = warp & 1;    // 2 M-warps * 64 rows
    const int wn   = warp >> 1;   // 4 N-warps * 32 cols
    const int gid  = lane >> 2;
    const int tig  = lane & 3;

    const int n0   = blockIdx.x * BN;
    const int ks   = blockIdx.y;
    const float* mat = (ks < 2) ? Gm : Bm;
    const int kmat0 = (ks & 1) * KLEN;
    const int kx0   = ks * KLEN;

    float acc[4][4][4];
#pragma unroll
    for (int mi = 0; mi < 4; ++mi)
#pragma unroll
        for (int ni = 0; ni < 4; ++ni)
#pragma unroll
            for (int q = 0; q < 4; ++q) acc[mi][ni][q] = 0.f;

    // ---- stage load: A (fp16 direct) + B (fp32 staging) ----
    auto issue = [&](int kt) {
        const int s = kt & (NSTAGES - 1);
        const uint32_t sA  = sbase + (uint32_t)s * STAGE_BYTES;
        const uint32_t sBF = sA + STAGE_A;
        const int kbx = kx0 + kt * BK;
        const int kbm = kmat0 + kt * BK;
#pragma unroll
        for (int it = 0; it < 2; ++it) {       // 512 x 16B : A tile
            int v   = tid + it * 256;
            int row = v >> 2;
            int c   = v & 3;
            cp16(sA + (uint32_t)(row * 80 + c * 16),
                 (const void*)&g_X16[(size_t)row * KDIM + kbx + c * 8]);
        }
#pragma unroll
        for (int it = 0; it < 4; ++it) {       // 1024 x 16B : B fp32 staging
            int v   = tid + it * 256;
            int row = v >> 3;
            int c   = v & 7;
            cp16(sBF + (uint32_t)(row * 128 + c * 16),
                 (const void*)&mat[(size_t)(n0 + row) * NBUS + kbm + c * 4]);
        }
    };

    // ---- convert B fp32 -> fp16 (padded rows) ----
    auto convert = [&](int kt) {
        const int s = kt & (NSTAGES - 1);
        const float*  bf  = (const float*)(smem + s * STAGE_BYTES + STAGE_A);
        __half*       b16 = (__half*)(smem + s * STAGE_BYTES + STAGE_A + STAGE_BF);
#pragma unroll
        for (int p = 0; p < 4; ++p) {
            int e = (tid + p * 256) * 4;
            float4 v = *(const float4*)(bf + e);
            int row = e >> 5, k = e & 31;
            __half2 h0 = __floats2half2_rn(v.x, v.y);
            __half2 h1 = __floats2half2_rn(v.z, v.w);
            uint2 pk;
            pk.x = *(uint32_t*)&h0;
            pk.y = *(uint32_t*)&h1;
            *(uint2*)(b16 + row * HSTRIDE + k) = pk;
        }
    };

    // prologue
#pragma unroll
    for (int p = 0; p < NSTAGES - 1; ++p) {
        issue(p);
        asm volatile("cp.async.commit_group;");
    }

    for (int kt = 0; kt < NKT; ++kt) {
        if (kt < NKT - 2)       asm volatile("cp.async.wait_group 2;");
        else if (kt == NKT - 2) asm volatile("cp.async.wait_group 1;");
        else                    asm volatile("cp.async.wait_group 0;");
        __syncthreads();

        int lkt = kt + NSTAGES - 1;
        if (lkt < NKT) {
            issue(lkt);
            asm volatile("cp.async.commit_group;");
        }
        convert(kt);
        __syncthreads();

        const int s = kt & (NSTAGES - 1);
        const __half* A16 = (const __half*)(smem + s * STAGE_BYTES);
        const __half* B16 = (const __half*)(smem + s * STAGE_BYTES + STAGE_A + STAGE_BF);

#pragma unroll
        for (int kk = 0; kk < 2; ++kk) {
            const int kb = kk * 16 + tig * 2;
            uint32_t a[4][4], bb[4][2];
#pragma unroll
            for (int mi = 0; mi < 4; ++mi) {
                int r0 = wm * 64 + mi * 16 + gid;
                a[mi][0] = *(const uint32_t*)(A16 + r0 * HSTRIDE + kb);
                a[mi][1] = *(const uint32_t*)(A16 + (r0 + 8) * HSTRIDE + kb);
                a[mi][2] = *(const uint32_t*)(A16 + r0 * HSTRIDE + kb + 8);
                a[mi][3] = *(const uint32_t*)(A16 + (r0 + 8) * HSTRIDE + kb + 8);
            }
#pragma unroll
            for (int ni = 0; ni < 4; ++ni) {
                int n = wn * 32 + ni * 8 + gid;
                bb[ni][0] = *(const uint32_t*)(B16 + n * HSTRIDE + kb);
                bb[ni][1] = *(const uint32_t*)(B16 + n * HSTRIDE + kb + 8);
            }
#pragma unroll
            for (int mi = 0; mi < 4; ++mi)
#pragma unroll
                for (int ni = 0; ni < 4; ++ni)
                    asm volatile(
                        "mma.sync.aligned.m16n8k16.row.col.f32.f16.f16.f32 "
                        "{%0,%1,%2,%3}, {%4,%5,%6,%7}, {%8,%9}, {%0,%1,%2,%3};"
                        : "+f"(acc[mi][ni][0]), "+f"(acc[mi][ni][1]),
                          "+f"(acc[mi][ni][2]), "+f"(acc[mi][ni][3])
                        : "r"(a[mi][0]), "r"(a[mi][1]),
                          "r"(a[mi][2]), "r"(a[mi][3]),
                          "r"(bb[ni][0]), "r"(bb[ni][1]));
        }
    }

    // write K-split partial
    float* outp = g_C + (size_t)ks * MROWS * NBUS;
#pragma unroll
    for (int mi = 0; mi < 4; ++mi) {
        int r0 = wm * 64 + mi * 16 + gid;
#pragma unroll
        for (int ni = 0; ni < 4; ++ni) {
            int col = n0 + wn * 32 + ni * 8 + tig * 2;
            *(float2*)&outp[(size_t)r0 * NBUS + col] =
                make_float2(acc[mi][ni][0], acc[mi][ni][1]);
            *(float2*)&outp[(size_t)(r0 + 8) * NBUS + col] =
                make_float2(acc[mi][ni][2], acc[mi][ni][3]);
        }
    }
}

// ---------------------------------------------------------------------------
// reduce K-split partials + power-flow epilogue (float4)
// ---------------------------------------------------------------------------
__global__ void epilogue_kernel(const float* __restrict__ Vm,
                                const float* __restrict__ Va,
                                const float* __restrict__ Pin,
                                const float* __restrict__ Qin,
                                float* __restrict__ out) {
    int idx = blockIdx.x * blockDim.x + threadIdx.x;   // over BATCH*NBUS/4
    if (idx >= BATCH * NBUS / 4) return;
    int e = idx * 4;
    int b = e >> 12;
    int i = e & (NBUS - 1);

    float4 U = make_float4(0.f, 0.f, 0.f, 0.f);
    float4 W = make_float4(0.f, 0.f, 0.f, 0.f);
#pragma unroll
    for (int ksp = 0; ksp < KSPLIT; ++ksp) {
        const float4 u = *(const float4*)&g_C[((size_t)(ksp * MROWS) + b) * NBUS + i];
        const float4 w = *(const float4*)&g_C[((size_t)(ksp * MROWS) + BATCH + b) * NBUS + i];
        U.x += u.x; U.y += u.y; U.z += u.z; U.w += u.w;
        W.x += w.x; W.y += w.y; W.z += w.z; W.w += w.w;
    }
    const float4 vm  = *(const float4*)&Vm[e];
    const float4 va  = *(const float4*)&Va[e];
    const float4 pin = *(const float4*)&Pin[e];
    const float4 qin = *(const float4*)&Qin[e];

    float Uv[4] = {U.x, U.y, U.z, U.w};
    float Wv[4] = {W.x, W.y, W.z, W.w};
    float vmv[4] = {vm.x, vm.y, vm.z, vm.w};
    float vav[4] = {va.x, va.y, va.z, va.w};
    float pv[4]  = {pin.x, pin.y, pin.z, pin.w};
    float qv[4]  = {qin.x, qin.y, qin.z, qin.w};
    float rp[4], rq[4];
#pragma unroll
    for (int q = 0; q < 4; ++q) {
        float sn, cs;
        sincosf(vav[q], &sn, &cs);
        rp[q] = vmv[q] * (cs * Uv[q] + sn * Wv[q]) - pv[q];
        rq[q] = vmv[q] * (sn * Uv[q] - cs * Wv[q]) - qv[q];
    }
    *(float4*)&out[e]                = make_float4(rp[0], rp[1], rp[2], rp[3]);
    *(float4*)&out[BATCH * NBUS + e] = make_float4(rq[0], rq[1], rq[2], rq[3]);
}

// ---------------------------------------------------------------------------
extern "C" void kernel_launch(void* const* d_in, const int* in_sizes, int n_in,
                              void* d_out, int out_size) {
    const float* Vm  = (const float*)d_in[0];
    const float* Va  = (const float*)d_in[1];
    const float* Pin = (const float*)d_in[2];
    const float* Qin = (const float*)d_in[3];
    const float* Gm  = (const float*)d_in[4];
    const float* Bm  = (const float*)d_in[5];
    float* out = (float*)d_out;

    cudaFuncSetAttribute(gemm_kernel,
                         cudaFuncAttributeMaxDynamicSharedMemorySize, SMEM_TOTAL);

    prep_kernel<<<(BATCH * NBUS / 4 + 255) / 256, 256>>>(Vm, Va);
    gemm_kernel<<<dim3(NBUS / BN, KSPLIT), THREADS, SMEM_TOTAL>>>(Gm, Bm);
    epilogue_kernel<<<(BATCH * NBUS / 4 + 255) / 256, 256>>>(Vm, Va, Pin, Qin, out);
}

// round 4
// speedup vs baseline: 1.5294x; 1.0951x over previous
#include <cuda_runtime.h>
#include <cuda_fp16.h>
#include <cstdint>

#define NBUS   4096
#define BATCH  64
#define MROWS  128        // 2*BATCH RHS rows
#define KDIM   8192       // 2*NBUS
#define BN     128
#define BK     32         // K per tile
#define KSPLIT 4
#define KLEN   (KDIM / KSPLIT)   // 2048
#define NKT    (KLEN / BK)       // 64
#define NSTAGES 4
#define THREADS 256

#define HSTRIDE 40                 // halves per padded row (80 B, 20-bank stride)
#define STAGE_A   10240            // fp16 X tile 128 x 32 (padded rows)
#define STAGE_BF  16384            // fp32 B staging 128 x 32
#define STAGE_B16 10240            // fp16 B tile
#define STAGE_BYTES (STAGE_A + STAGE_BF + STAGE_B16)   // 36864
#define SMEM_TOTAL  (NSTAGES * STAGE_BYTES)            // 147456

// Scratch (no runtime allocation allowed)
__device__ __half g_X16[MROWS * KDIM];          // 2 MB stacked RHS (fp16)
__device__ float  g_C[KSPLIT * MROWS * NBUS];   // 8 MB K-split partials

// ---------------------------------------------------------------------------
// Kernel 1: build X (fp16), 4 elements per thread, MUFU sincos
// ---------------------------------------------------------------------------
__global__ void prep_kernel(const float* __restrict__ Vm,
                            const float* __restrict__ Va) {
    int t = blockIdx.x * blockDim.x + threadIdx.x;   // over BATCH*NBUS/4
    if (t >= BATCH * NBUS / 4) return;
    int e = t * 4;
    int b = e >> 12;
    int j = e & (NBUS - 1);
    const float4 vm = *(const float4*)&Vm[e];
    const float4 va = *(const float4*)&Va[e];
    float vmv[4] = {vm.x, vm.y, vm.z, vm.w};
    float vav[4] = {va.x, va.y, va.z, va.w};
    __half hc[4], hs[4], hn[4];
#pragma unroll
    for (int q = 0; q < 4; ++q) {
        float sn, cs;
        __sincosf(vav[q], &sn, &cs);
        hc[q] = __float2half_rn(vmv[q] * cs);
        hs[q] = __float2half_rn(vmv[q] * sn);
        hn[q] = __hneg(hc[q]);
    }
    *(uint2*)&g_X16[b * KDIM + j]                  = *(uint2*)hc;
    *(uint2*)&g_X16[b * KDIM + NBUS + j]           = *(uint2*)hs;
    *(uint2*)&g_X16[(BATCH + b) * KDIM + j]        = *(uint2*)hs;
    *(uint2*)&g_X16[(BATCH + b) * KDIM + NBUS + j] = *(uint2*)hn;
}

// ---------------------------------------------------------------------------
__device__ __forceinline__ void cp16(uint32_t saddr, const void* gptr) {
    asm volatile("cp.async.cg.shared.global [%0], [%1], 16;\n"
                 :: "r"(saddr), "l"(gptr));
}

#define LDSM4(r0, r1, r2, r3, addr)                                           \
    asm volatile("ldmatrix.sync.aligned.m8n8.x4.shared.b16 "                  \
                 "{%0,%1,%2,%3}, [%4];"                                       \
                 : "=r"(r0), "=r"(r1), "=r"(r2), "=r"(r3) : "r"(addr))

// ---------------------------------------------------------------------------
// fp16 GEMM: C[128,4096] = X[128,8192] @ [G|B]^T  (K-split partials)
// ---------------------------------------------------------------------------
__global__ void __launch_bounds__(THREADS)
gemm_kernel(const float* __restrict__ Gm, const float* __restrict__ Bm) {
    extern __shared__ char smem[];
    uint32_t sbase;
    asm("{ .reg .u64 t; cvta.to.shared.u64 t, %1; cvt.u32.u64 %0, t; }"
        : "=r"(sbase) : "l"(smem));

    const int tid  = threadIdx.x;
    const int lane = tid & 31;
    const int warp = tid >> 5;
    const int wm   = warp & 1;    // 2 M-warps * 64 rows
    const int wn   = warp >> 1;   // 4 N-warps * 32 cols

    const int n0   = blockIdx.x * BN;
    const int ks   = blockIdx.y;
    const float* mat = (ks < 2) ? Gm : Bm;
    const int kmat0 = (ks & 1) * KLEN;
    const int kx0   = ks * KLEN;

    // ldmatrix per-lane byte offsets (within a stage's A16 / B16 region)
    const int lm  = lane >> 3;       // which 8x8 matrix this lane addresses
    const int l8  = lane & 7;
    uint32_t aoff[4], boff[2];
#pragma unroll
    for (int mi = 0; mi < 4; ++mi) {
        int row = wm * 64 + mi * 16 + ((lm & 1) << 3) + l8;
        aoff[mi] = (uint32_t)(row * HSTRIDE + ((lm >> 1) << 3)) * 2u;
    }
#pragma unroll
    for (int np = 0; np < 2; ++np) {
        int n = wn * 32 + np * 16 + ((lm >> 1) << 3) + l8;
        boff[np] = (uint32_t)(n * HSTRIDE + ((lm & 1) << 3)) * 2u;
    }

    float acc[4][4][4];
#pragma unroll
    for (int mi = 0; mi < 4; ++mi)
#pragma unroll
        for (int ni = 0; ni < 4; ++ni)
#pragma unroll
            for (int q = 0; q < 4; ++q) acc[mi][ni][q] = 0.f;

    // ---- stage load: A (fp16 direct) + B (fp32 staging) ----
    auto issue = [&](int kt) {
        const int s = kt & (NSTAGES - 1);
        const uint32_t sA  = sbase + (uint32_t)s * STAGE_BYTES;
        const uint32_t sBF = sA + STAGE_A;
        const int kbx = kx0 + kt * BK;
        const int kbm = kmat0 + kt * BK;
#pragma unroll
        for (int it = 0; it < 2; ++it) {       // 512 x 16B : A tile
            int v   = tid + it * 256;
            int row = v >> 2;
            int c   = v & 3;
            cp16(sA + (uint32_t)(row * 80 + c * 16),
                 (const void*)&g_X16[(size_t)row * KDIM + kbx + c * 8]);
        }
#pragma unroll
        for (int it = 0; it < 4; ++it) {       // 1024 x 16B : B fp32 staging
            int v   = tid + it * 256;
            int row = v >> 3;
            int c   = v & 7;
            cp16(sBF + (uint32_t)(row * 128 + c * 16),
                 (const void*)&mat[(size_t)(n0 + row) * NBUS + kbm + c * 4]);
        }
    };

    // ---- convert B fp32 -> fp16 (same-thread as the cp.async writes) ----
    auto convert = [&](int kt) {
        const int s = kt & (NSTAGES - 1);
        const float*  bf  = (const float*)(smem + s * STAGE_BYTES + STAGE_A);
        __half*       b16 = (__half*)(smem + s * STAGE_BYTES + STAGE_A + STAGE_BF);
#pragma unroll
        for (int p = 0; p < 4; ++p) {
            int e = (tid + p * 256) * 4;
            float4 v = *(const float4*)(bf + e);
            int row = e >> 5, k = e & 31;
            __half2 h0 = __floats2half2_rn(v.x, v.y);
            __half2 h1 = __floats2half2_rn(v.z, v.w);
            uint2 pk;
            pk.x = *(uint32_t*)&h0;
            pk.y = *(uint32_t*)&h1;
            *(uint2*)(b16 + row * HSTRIDE + k) = pk;
        }
    };

    // prologue: stages 0..2 in flight, convert stage 0
#pragma unroll
    for (int p = 0; p < NSTAGES - 1; ++p) {
        issue(p);
        asm volatile("cp.async.commit_group;");
    }
    asm volatile("cp.async.wait_group 2;");
    convert(0);

    for (int kt = 0; kt < NKT; ++kt) {
        __syncthreads();   // publishes convert(kt); fences mma(kt-1) readers

        if (kt + 3 < NKT) {
            issue(kt + 3);
            asm volatile("cp.async.commit_group;");
        }
        if (kt + 1 < NKT) {
            if (kt + 3 < NKT)       asm volatile("cp.async.wait_group 2;");
            else if (kt + 3 == NKT) asm volatile("cp.async.wait_group 1;");
            else                    asm volatile("cp.async.wait_group 0;");
            convert(kt + 1);
        }

        const int s = kt & (NSTAGES - 1);
        const uint32_t sA16 = sbase + (uint32_t)s * STAGE_BYTES;
        const uint32_t sB16 = sA16 + STAGE_A + STAGE_BF;

#pragma unroll
        for (int kk = 0; kk < 2; ++kk) {
            const uint32_t kbyte = kk * 32;   // 16 halves
            uint32_t a[4][4], bb[4][2];
#pragma unroll
            for (int mi = 0; mi < 4; ++mi)
                LDSM4(a[mi][0], a[mi][1], a[mi][2], a[mi][3],
                      sA16 + aoff[mi] + kbyte);
#pragma unroll
            for (int np = 0; np < 2; ++np)
                LDSM4(bb[np * 2][0], bb[np * 2][1], bb[np * 2 + 1][0],
                      bb[np * 2 + 1][1], sB16 + boff[np] + kbyte);
#pragma unroll
            for (int mi = 0; mi < 4; ++mi)
#pragma unroll
                for (int ni = 0; ni < 4; ++ni)
                    asm volatile(
                        "mma.sync.aligned.m16n8k16.row.col.f32.f16.f16.f32 "
                        "{%0,%1,%2,%3}, {%4,%5,%6,%7}, {%8,%9}, {%0,%1,%2,%3};"
                        : "+f"(acc[mi][ni][0]), "+f"(acc[mi][ni][1]),
                          "+f"(acc[mi][ni][2]), "+f"(acc[mi][ni][3])
                        : "r"(a[mi][0]), "r"(a[mi][1]),
                          "r"(a[mi][2]), "r"(a[mi][3]),
                          "r"(bb[ni][0]), "r"(bb[ni][1]));
        }
    }

    // write K-split partial
    const int gid = lane >> 2;
    const int tig = lane & 3;
    float* outp = g_C + (size_t)ks * MROWS * NBUS;
#pragma unroll
    for (int mi = 0; mi < 4; ++mi) {
        int r0 = wm * 64 + mi * 16 + gid;
#pragma unroll
        for (int ni = 0; ni < 4; ++ni) {
            int col = n0 + wn * 32 + ni * 8 + tig * 2;
            *(float2*)&outp[(size_t)r0 * NBUS + col] =
                make_float2(acc[mi][ni][0], acc[mi][ni][1]);
            *(float2*)&outp[(size_t)(r0 + 8) * NBUS + col] =
                make_float2(acc[mi][ni][2], acc[mi][ni][3]);
        }
    }
}

// ---------------------------------------------------------------------------
// reduce K-split partials + power-flow epilogue (float4, MUFU sincos)
// ---------------------------------------------------------------------------
__global__ void epilogue_kernel(const float* __restrict__ Vm,
                                const float* __restrict__ Va,
                                const float* __restrict__ Pin,
                                const float* __restrict__ Qin,
                                float* __restrict__ out) {
    int idx = blockIdx.x * blockDim.x + threadIdx.x;   // over BATCH*NBUS/4
    if (idx >= BATCH * NBUS / 4) return;
    int e = idx * 4;
    int b = e >> 12;
    int i = e & (NBUS - 1);

    float4 U = make_float4(0.f, 0.f, 0.f, 0.f);
    float4 W = make_float4(0.f, 0.f, 0.f, 0.f);
#pragma unroll
    for (int ksp = 0; ksp < KSPLIT; ++ksp) {
        const float4 u = *(const float4*)&g_C[((size_t)(ksp * MROWS) + b) * NBUS + i];
        const float4 w = *(const float4*)&g_C[((size_t)(ksp * MROWS) + BATCH + b) * NBUS + i];
        U.x += u.x; U.y += u.y; U.z += u.z; U.w += u.w;
        W.x += w.x; W.y += w.y; W.z += w.z; W.w += w.w;
    }
    const float4 vm  = *(const float4*)&Vm[e];
    const float4 va  = *(const float4*)&Va[e];
    const float4 pin = *(const float4*)&Pin[e];
    const float4 qin = *(const float4*)&Qin[e];

    float Uv[4] = {U.x, U.y, U.z, U.w};
    float Wv[4] = {W.x, W.y, W.z, W.w};
    float vmv[4] = {vm.x, vm.y, vm.z, vm.w};
    float vav[4] = {va.x, va.y, va.z, va.w};
    float pv[4]  = {pin.x, pin.y, pin.z, pin.w};
    float qv[4]  = {qin.x, qin.y, qin.z, qin.w};
    float rp[4], rq[4];
#pragma unroll
    for (int q = 0; q < 4; ++q) {
        float sn, cs;
        __sincosf(vav[q], &sn, &cs);
        rp[q] = vmv[q] * (cs * Uv[q] + sn * Wv[q]) - pv[q];
        rq[q] = vmv[q] * (sn * Uv[q] - cs * Wv[q]) - qv[q];
    }
    *(float4*)&out[e]                = make_float4(rp[0], rp[1], rp[2], rp[3]);
    *(float4*)&out[BATCH * NBUS + e] = make_float4(rq[0], rq[1], rq[2], rq[3]);
}

// ---------------------------------------------------------------------------
extern "C" void kernel_launch(void* const* d_in, const int* in_sizes, int n_in,
                              void* d_out, int out_size) {
    const float* Vm  = (const float*)d_in[0];
    const float* Va  = (const float*)d_in[1];
    const float* Pin = (const float*)d_in[2];
    const float* Qin = (const float*)d_in[3];
    const float* Gm  = (const float*)d_in[4];
    const float* Bm  = (const float*)d_in[5];
    float* out = (float*)d_out;

    cudaFuncSetAttribute(gemm_kernel,
                         cudaFuncAttributeMaxDynamicSharedMemorySize, SMEM_TOTAL);

    prep_kernel<<<(BATCH * NBUS / 4 + 255) / 256, 256>>>(Vm, Va);
    gemm_kernel<<<dim3(NBUS / BN, KSPLIT), THREADS, SMEM_TOTAL>>>(Gm, Bm);
    epilogue_kernel<<<(BATCH * NBUS / 4 + 255) / 256, 256>>>(Vm, Va, Pin, Qin, out);
}

// round 5
// speedup vs baseline: 1.8447x; 1.2062x over previous
#include <cuda_runtime.h>
#include <cuda_fp16.h>
#include <cstdint>

#define NBUS   4096
#define BATCH  64
#define MROWS  128        // 2*BATCH RHS rows
#define KDIM   8192       // 2*NBUS
#define BN     128
#define BK     32         // K per tile
#define KSPLIT 4
#define KLEN   (KDIM / KSPLIT)   // 2048
#define NKT    (KLEN / BK)       // 64
#define NSTAGES 4
#define THREADS 384               // 8 consumer warps + 4 producer warps

#define HSTRIDE 40                 // halves per padded row (80 B, 20-bank stride)
#define STAGE_A   10240            // fp16 X tile 128 x 32 (padded rows)
#define STAGE_BF  16384            // fp32 B staging 128 x 32
#define STAGE_B16 10240            // fp16 B tile
#define STAGE_BYTES (STAGE_A + STAGE_BF + STAGE_B16)   // 36864
#define SMEM_TOTAL  (NSTAGES * STAGE_BYTES)            // 147456

// named barrier ids: FULL[s]=1+s, FREE[s]=5+s; count = all 384 threads
#define BAR_CNT 384

// Scratch (no runtime allocation allowed)
__device__ __half  g_X16[MROWS * KDIM];          // 2 MB stacked RHS (fp16)
__device__ float   g_C[KSPLIT * MROWS * NBUS];   // 8 MB K-split partials
__device__ float2  g_trig[BATCH * NBUS];         // 2 MB cached (cos, sin)

// ---------------------------------------------------------------------------
// Kernel 1: build X (fp16) + cache (cos,sin) for the epilogue
// ---------------------------------------------------------------------------
__global__ void prep_kernel(const float* __restrict__ Vm,
                            const float* __restrict__ Va) {
    int t = blockIdx.x * blockDim.x + threadIdx.x;   // over BATCH*NBUS/4
    if (t >= BATCH * NBUS / 4) return;
    int e = t * 4;
    int b = e >> 12;
    int j = e & (NBUS - 1);
    const float4 vm = *(const float4*)&Vm[e];
    const float4 va = *(const float4*)&Va[e];
    float vmv[4] = {vm.x, vm.y, vm.z, vm.w};
    float vav[4] = {va.x, va.y, va.z, va.w};
    __half hc[4], hs[4], hn[4];
    float2 tr[4];
#pragma unroll
    for (int q = 0; q < 4; ++q) {
        float sn, cs;
        __sincosf(vav[q], &sn, &cs);
        tr[q] = make_float2(cs, sn);
        hc[q] = __float2half_rn(vmv[q] * cs);
        hs[q] = __float2half_rn(vmv[q] * sn);
        hn[q] = __hneg(hc[q]);
    }
    *(uint2*)&g_X16[b * KDIM + j]                  = *(uint2*)hc;
    *(uint2*)&g_X16[b * KDIM + NBUS + j]           = *(uint2*)hs;
    *(uint2*)&g_X16[(BATCH + b) * KDIM + j]        = *(uint2*)hs;
    *(uint2*)&g_X16[(BATCH + b) * KDIM + NBUS + j] = *(uint2*)hn;
    *(float4*)&g_trig[e]     = make_float4(tr[0].x, tr[0].y, tr[1].x, tr[1].y);
    *(float4*)&g_trig[e + 2] = make_float4(tr[2].x, tr[2].y, tr[3].x, tr[3].y);
}

// ---------------------------------------------------------------------------
__device__ __forceinline__ void cp16(uint32_t saddr, const void* gptr) {
    asm volatile("cp.async.cg.shared.global [%0], [%1], 16;\n"
                 :: "r"(saddr), "l"(gptr));
}

__device__ __forceinline__ void bar_sync(int id) {
    asm volatile("bar.sync %0, %1;" :: "r"(id), "n"(BAR_CNT) : "memory");
}
__device__ __forceinline__ void bar_arrive(int id) {
    asm volatile("bar.arrive %0, %1;" :: "r"(id), "n"(BAR_CNT) : "memory");
}

#define LDSM4(r0, r1, r2, r3, addr)                                           \
    asm volatile("ldmatrix.sync.aligned.m8n8.x4.shared.b16 "                  \
                 "{%0,%1,%2,%3}, [%4];"                                       \
                 : "=r"(r0), "=r"(r1), "=r"(r2), "=r"(r3) : "r"(addr))

// ---------------------------------------------------------------------------
// Warp-specialized fp16 GEMM: C[128,4096] = X[128,8192] @ [G|B]^T
//   warps 0-7  : consumers (ldmatrix + mma)
//   warps 8-11 : producers (cp.async + f32->f16 convert)
// ---------------------------------------------------------------------------
__global__ void __launch_bounds__(THREADS)
gemm_kernel(const float* __restrict__ Gm, const float* __restrict__ Bm) {
    extern __shared__ char smem[];
    uint32_t sbase;
    asm("{ .reg .u64 t; cvta.to.shared.u64 t, %1; cvt.u32.u64 %0, t; }"
        : "=r"(sbase) : "l"(smem));

    const int tid  = threadIdx.x;
    const int lane = tid & 31;
    const int warp = tid >> 5;

    const int n0   = blockIdx.x * BN;
    const int ks   = blockIdx.y;
    const float* mat = (ks < 2) ? Gm : Bm;
    const int kmat0 = (ks & 1) * KLEN;
    const int kx0   = ks * KLEN;

    if (warp >= 8) {
        // ================= PRODUCER =================
        const int ptid = tid - 256;   // 0..127

        auto issue = [&](int kt) {
            const int s = kt & (NSTAGES - 1);
            const uint32_t sA  = sbase + (uint32_t)s * STAGE_BYTES;
            const uint32_t sBF = sA + STAGE_A;
            const int kbx = kx0 + kt * BK;
            const int kbm = kmat0 + kt * BK;
#pragma unroll
            for (int it = 0; it < 4; ++it) {   // 512 x 16B : A tile
                int v   = ptid + it * 128;
                int row = v >> 2;
                int c   = v & 3;
                cp16(sA + (uint32_t)(row * 80 + c * 16),
                     (const void*)&g_X16[(size_t)row * KDIM + kbx + c * 8]);
            }
#pragma unroll
            for (int it = 0; it < 8; ++it) {   // 1024 x 16B : B fp32 staging
                int v   = ptid + it * 128;
                int row = v >> 3;
                int c   = v & 7;
                cp16(sBF + (uint32_t)(row * 128 + c * 16),
                     (const void*)&mat[(size_t)(n0 + row) * NBUS + kbm + c * 4]);
            }
        };
        auto convert = [&](int kt) {
            const int s = kt & (NSTAGES - 1);
            const float* bf  = (const float*)(smem + s * STAGE_BYTES + STAGE_A);
            __half*      b16 = (__half*)(smem + s * STAGE_BYTES + STAGE_A + STAGE_BF);
#pragma unroll
            for (int p = 0; p < 8; ++p) {
                int e = (ptid + p * 128) * 4;
                float4 v = *(const float4*)(bf + e);
                int row = e >> 5, k = e & 31;
                __half2 h0 = __floats2half2_rn(v.x, v.y);
                __half2 h1 = __floats2half2_rn(v.z, v.w);
                uint2 pk;
                pk.x = *(uint32_t*)&h0;
                pk.y = *(uint32_t*)&h1;
                *(uint2*)(b16 + row * HSTRIDE + k) = pk;
            }
        };

        for (int kt = 0; kt < NKT; ++kt) {
            if (kt >= NSTAGES) bar_sync(5 + (kt & 3));      // FREE[s]
            issue(kt);
            asm volatile("cp.async.commit_group;");
            if (kt >= 2) {
                asm volatile("cp.async.wait_group 2;");
                convert(kt - 2);
                bar_arrive(1 + ((kt - 2) & 3));             // FULL[s]
            }
        }
        asm volatile("cp.async.wait_group 0;");
        convert(NKT - 2);
        bar_arrive(1 + ((NKT - 2) & 3));
        convert(NKT - 1);
        bar_arrive(1 + ((NKT - 1) & 3));
    } else {
        // ================= CONSUMER =================
        const int wm = warp & 1;    // 2 M-warps * 64 rows
        const int wn = warp >> 1;   // 4 N-warps * 32 cols
        const int lm = lane >> 3;
        const int l8 = lane & 7;

        uint32_t aoff[4], boff[2];
#pragma unroll
        for (int mi = 0; mi < 4; ++mi) {
            int row = wm * 64 + mi * 16 + ((lm & 1) << 3) + l8;
            aoff[mi] = (uint32_t)(row * HSTRIDE + ((lm >> 1) << 3)) * 2u;
        }
#pragma unroll
        for (int np = 0; np < 2; ++np) {
            int n = wn * 32 + np * 16 + ((lm >> 1) << 3) + l8;
            boff[np] = (uint32_t)(n * HSTRIDE + ((lm & 1) << 3)) * 2u;
        }

        float acc[4][4][4];
#pragma unroll
        for (int mi = 0; mi < 4; ++mi)
#pragma unroll
            for (int ni = 0; ni < 4; ++ni)
#pragma unroll
                for (int q = 0; q < 4; ++q) acc[mi][ni][q] = 0.f;

        for (int kt = 0; kt < NKT; ++kt) {
            const int s = kt & 3;
            bar_sync(1 + s);                                // FULL[s]
            const uint32_t sA16 = sbase + (uint32_t)s * STAGE_BYTES;
            const uint32_t sB16 = sA16 + STAGE_A + STAGE_BF;

#pragma unroll
            for (int kk = 0; kk < 2; ++kk) {
                const uint32_t kbyte = kk * 32;   // 16 halves
                uint32_t a[4][4], bb[4][2];
#pragma unroll
                for (int mi = 0; mi < 4; ++mi)
                    LDSM4(a[mi][0], a[mi][1], a[mi][2], a[mi][3],
                          sA16 + aoff[mi] + kbyte);
#pragma unroll
                for (int np = 0; np < 2; ++np)
                    LDSM4(bb[np * 2][0], bb[np * 2][1], bb[np * 2 + 1][0],
                          bb[np * 2 + 1][1], sB16 + boff[np] + kbyte);
#pragma unroll
                for (int mi = 0; mi < 4; ++mi)
#pragma unroll
                    for (int ni = 0; ni < 4; ++ni)
                        asm volatile(
                            "mma.sync.aligned.m16n8k16.row.col.f32.f16.f16.f32 "
                            "{%0,%1,%2,%3}, {%4,%5,%6,%7}, {%8,%9}, {%0,%1,%2,%3};"
                            : "+f"(acc[mi][ni][0]), "+f"(acc[mi][ni][1]),
                              "+f"(acc[mi][ni][2]), "+f"(acc[mi][ni][3])
                            : "r"(a[mi][0]), "r"(a[mi][1]),
                              "r"(a[mi][2]), "r"(a[mi][3]),
                              "r"(bb[ni][0]), "r"(bb[ni][1]));
            }
            bar_arrive(5 + s);                              // FREE[s]
        }

        // write K-split partial
        const int gid = lane >> 2;
        const int tig = lane & 3;
        float* outp = g_C + (size_t)ks * MROWS * NBUS;
#pragma unroll
        for (int mi = 0; mi < 4; ++mi) {
            int r0 = wm * 64 + mi * 16 + gid;
#pragma unroll
            for (int ni = 0; ni < 4; ++ni) {
                int col = n0 + wn * 32 + ni * 8 + tig * 2;
                *(float2*)&outp[(size_t)r0 * NBUS + col] =
                    make_float2(acc[mi][ni][0], acc[mi][ni][1]);
                *(float2*)&outp[(size_t)(r0 + 8) * NBUS + col] =
                    make_float2(acc[mi][ni][2], acc[mi][ni][3]);
            }
        }
    }
}

// ---------------------------------------------------------------------------
// reduce K-split partials + power-flow epilogue (trig from cache, no MUFU)
// ---------------------------------------------------------------------------
__global__ void epilogue_kernel(const float* __restrict__ Vm,
                                const float* __restrict__ Pin,
                                const float* __restrict__ Qin,
                                float* __restrict__ out) {
    int idx = blockIdx.x * blockDim.x + threadIdx.x;   // over BATCH*NBUS/4
    if (idx >= BATCH * NBUS / 4) return;
    int e = idx * 4;
    int b = e >> 12;
    int i = e & (NBUS - 1);

    float4 U = make_float4(0.f, 0.f, 0.f, 0.f);
    float4 W = make_float4(0.f, 0.f, 0.f, 0.f);
#pragma unroll
    for (int ksp = 0; ksp < KSPLIT; ++ksp) {
        const float4 u = *(const float4*)&g_C[((size_t)(ksp * MROWS) + b) * NBUS + i];
        const float4 w = *(const float4*)&g_C[((size_t)(ksp * MROWS) + BATCH + b) * NBUS + i];
        U.x += u.x; U.y += u.y; U.z += u.z; U.w += u.w;
        W.x += w.x; W.y += w.y; W.z += w.z; W.w += w.w;
    }
    const float4 vm  = *(const float4*)&Vm[e];
    const float4 pin = *(const float4*)&Pin[e];
    const float4 qin = *(const float4*)&Qin[e];
    const float4 t01 = *(const float4*)&g_trig[e];
    const float4 t23 = *(const float4*)&g_trig[e + 2];

    float Uv[4]  = {U.x, U.y, U.z, U.w};
    float Wv[4]  = {W.x, W.y, W.z, W.w};
    float vmv[4] = {vm.x, vm.y, vm.z, vm.w};
    float pv[4]  = {pin.x, pin.y, pin.z, pin.w};
    float qv[4]  = {qin.x, qin.y, qin.z, qin.w};
    float csv[4] = {t01.x, t01.z, t23.x, t23.z};
    float snv[4] = {t01.y, t01.w, t23.y, t23.w};
    float rp[4], rq[4];
#pragma unroll
    for (int q = 0; q < 4; ++q) {
        rp[q] = vmv[q] * (csv[q] * Uv[q] + snv[q] * Wv[q]) - pv[q];
        rq[q] = vmv[q] * (snv[q] * Uv[q] - csv[q] * Wv[q]) - qv[q];
    }
    *(float4*)&out[e]                = make_float4(rp[0], rp[1], rp[2], rp[3]);
    *(float4*)&out[BATCH * NBUS + e] = make_float4(rq[0], rq[1], rq[2], rq[3]);
}

// ---------------------------------------------------------------------------
extern "C" void kernel_launch(void* const* d_in, const int* in_sizes, int n_in,
                              void* d_out, int out_size) {
    const float* Vm  = (const float*)d_in[0];
    const float* Va  = (const float*)d_in[1];
    const float* Pin = (const float*)d_in[2];
    const float* Qin = (const float*)d_in[3];
    const float* Gm  = (const float*)d_in[4];
    const float* Bm  = (const float*)d_in[5];
    float* out = (float*)d_out;

    cudaFuncSetAttribute(gemm_kernel,
                         cudaFuncAttributeMaxDynamicSharedMemorySize, SMEM_TOTAL);

    prep_kernel<<<(BATCH * NBUS / 4 + 255) / 256, 256>>>(Vm, Va);
    gemm_kernel<<<dim3(NBUS / BN, KSPLIT), THREADS, SMEM_TOTAL>>>(Gm, Bm);
    epilogue_kernel<<<(BATCH * NBUS / 4 + 255) / 256, 256>>>(Vm, Pin, Qin, out);
}

// round 6
// speedup vs baseline: 1.8459x; 1.0006x over previous
#include <cuda_runtime.h>
#include <cuda_fp16.h>
#include <cstdint>

#define NBUS   4096
#define BATCH  64
#define MROWS  128        // 2*BATCH RHS rows
#define KDIM   8192       // 2*NBUS
#define BN     128
#define BK     32         // K per tile
#define KSPLIT 4
#define KLEN   (KDIM / KSPLIT)   // 2048
#define NKT    (KLEN / BK)       // 64
#define NSTAGES 4
#define THREADS 384               // 8 consumer warps + 4 producer warps

#define HSTRIDE 40                 // halves per padded row (80 B, 20-bank stride)
#define STAGE_A   10240            // fp16 X tile 128 x 32 (padded rows)
#define STAGE_BF  16384            // fp32 B staging 128 x 32
#define STAGE_B16 10240            // fp16 B tile
#define STAGE_BYTES (STAGE_A + STAGE_BF + STAGE_B16)   // 36864
#define SMEM_TOTAL  (NSTAGES * STAGE_BYTES)            // 147456

// named barrier ids: FULL[s]=1+s, FREE[s]=5+s; count = all 384 threads
#define BAR_CNT 384

// Scratch (no runtime allocation allowed)
__device__ __half  g_X16[MROWS * KDIM];          // 2 MB stacked RHS (fp16)
__device__ float   g_C[KSPLIT * MROWS * NBUS];   // 8 MB K-split partials
__device__ float2  g_trig[BATCH * NBUS];         // 2 MB cached (cos, sin)

// ---------------------------------------------------------------------------
// Kernel 1: build X (fp16) + cache (cos,sin); 2 elems/thread for occupancy
// ---------------------------------------------------------------------------
__global__ void prep_kernel(const float* __restrict__ Vm,
                            const float* __restrict__ Va) {
    int t = blockIdx.x * blockDim.x + threadIdx.x;   // over BATCH*NBUS/2
    if (t >= BATCH * NBUS / 2) return;
    int e = t * 2;
    int b = e >> 12;
    int j = e & (NBUS - 1);
    const float2 vm = *(const float2*)&Vm[e];
    const float2 va = *(const float2*)&Va[e];
    float sn0, cs0, sn1, cs1;
    __sincosf(va.x, &sn0, &cs0);
    __sincosf(va.y, &sn1, &cs1);
    __half2 hc = __floats2half2_rn(vm.x * cs0, vm.y * cs1);
    __half2 hs = __floats2half2_rn(vm.x * sn0, vm.y * sn1);
    __half2 hn = __hneg2(hc);
    *(uint32_t*)&g_X16[b * KDIM + j]                  = *(uint32_t*)&hc;
    *(uint32_t*)&g_X16[b * KDIM + NBUS + j]           = *(uint32_t*)&hs;
    *(uint32_t*)&g_X16[(BATCH + b) * KDIM + j]        = *(uint32_t*)&hs;
    *(uint32_t*)&g_X16[(BATCH + b) * KDIM + NBUS + j] = *(uint32_t*)&hn;
    *(float4*)&g_trig[e] = make_float4(cs0, sn0, cs1, sn1);
}

// ---------------------------------------------------------------------------
__device__ __forceinline__ void cp16(uint32_t saddr, const void* gptr) {
    asm volatile("cp.async.cg.shared.global [%0], [%1], 16;\n"
                 :: "r"(saddr), "l"(gptr));
}

__device__ __forceinline__ void bar_sync(int id) {
    asm volatile("bar.sync %0, %1;" :: "r"(id), "n"(BAR_CNT) : "memory");
}
__device__ __forceinline__ void bar_arrive(int id) {
    asm volatile("bar.arrive %0, %1;" :: "r"(id), "n"(BAR_CNT) : "memory");
}

#define LDSM4(r0, r1, r2, r3, addr)                                           \
    asm volatile("ldmatrix.sync.aligned.m8n8.x4.shared.b16 "                  \
                 "{%0,%1,%2,%3}, [%4];"                                       \
                 : "=r"(r0), "=r"(r1), "=r"(r2), "=r"(r3) : "r"(addr))

// ---------------------------------------------------------------------------
// Warp-specialized fp16 GEMM: C[128,4096] = X[128,8192] @ [G|B]^T
//   warps 0-7  : consumers (ldmatrix burst, early FREE, mma burst)
//   warps 8-11 : producers (cp.async + f32->f16 convert)
// ---------------------------------------------------------------------------
__global__ void __launch_bounds__(THREADS)
gemm_kernel(const float* __restrict__ Gm, const float* __restrict__ Bm) {
    extern __shared__ char smem[];
    uint32_t sbase;
    asm("{ .reg .u64 t; cvta.to.shared.u64 t, %1; cvt.u32.u64 %0, t; }"
        : "=r"(sbase) : "l"(smem));

    const int tid  = threadIdx.x;
    const int lane = tid & 31;
    const int warp = tid >> 5;

    const int n0   = blockIdx.x * BN;
    const int ks   = blockIdx.y;
    const float* mat = (ks < 2) ? Gm : Bm;
    const int kmat0 = (ks & 1) * KLEN;
    const int kx0   = ks * KLEN;

    if (warp >= 8) {
        // ================= PRODUCER =================
        const int ptid = tid - 256;   // 0..127

        auto issue = [&](int kt) {
            const int s = kt & (NSTAGES - 1);
            const uint32_t sA  = sbase + (uint32_t)s * STAGE_BYTES;
            const uint32_t sBF = sA + STAGE_A;
            const int kbx = kx0 + kt * BK;
            const int kbm = kmat0 + kt * BK;
#pragma unroll
            for (int it = 0; it < 4; ++it) {   // 512 x 16B : A tile
                int v   = ptid + it * 128;
                int row = v >> 2;
                int c   = v & 3;
                cp16(sA + (uint32_t)(row * 80 + c * 16),
                     (const void*)&g_X16[(size_t)row * KDIM + kbx + c * 8]);
            }
#pragma unroll
            for (int it = 0; it < 8; ++it) {   // 1024 x 16B : B fp32 staging
                int v   = ptid + it * 128;
                int row = v >> 3;
                int c   = v & 7;
                cp16(sBF + (uint32_t)(row * 128 + c * 16),
                     (const void*)&mat[(size_t)(n0 + row) * NBUS + kbm + c * 4]);
            }
        };
        auto convert = [&](int kt) {
            const int s = kt & (NSTAGES - 1);
            const float* bf  = (const float*)(smem + s * STAGE_BYTES + STAGE_A);
            __half*      b16 = (__half*)(smem + s * STAGE_BYTES + STAGE_A + STAGE_BF);
#pragma unroll
            for (int p = 0; p < 8; ++p) {
                int e = (ptid + p * 128) * 4;
                float4 v = *(const float4*)(bf + e);
                int row = e >> 5, k = e & 31;
                __half2 h0 = __floats2half2_rn(v.x, v.y);
                __half2 h1 = __floats2half2_rn(v.z, v.w);
                uint2 pk;
                pk.x = *(uint32_t*)&h0;
                pk.y = *(uint32_t*)&h1;
                *(uint2*)(b16 + row * HSTRIDE + k) = pk;
            }
        };

        for (int kt = 0; kt < NKT; ++kt) {
            if (kt >= NSTAGES) bar_sync(5 + (kt & 3));      // FREE[s]
            issue(kt);
            asm volatile("cp.async.commit_group;");
            if (kt >= 2) {
                asm volatile("cp.async.wait_group 2;");
                convert(kt - 2);
                bar_arrive(1 + ((kt - 2) & 3));             // FULL[s]
            }
        }
        asm volatile("cp.async.wait_group 0;");
        convert(NKT - 2);
        bar_arrive(1 + ((NKT - 2) & 3));
        convert(NKT - 1);
        bar_arrive(1 + ((NKT - 1) & 3));
    } else {
        // ================= CONSUMER =================
        const int wm = warp & 1;    // 2 M-warps * 64 rows
        const int wn = warp >> 1;   // 4 N-warps * 32 cols
        const int lm = lane >> 3;
        const int l8 = lane & 7;

        uint32_t aoff[4], boff[2];
#pragma unroll
        for (int mi = 0; mi < 4; ++mi) {
            int row = wm * 64 + mi * 16 + ((lm & 1) << 3) + l8;
            aoff[mi] = (uint32_t)(row * HSTRIDE + ((lm >> 1) << 3)) * 2u;
        }
#pragma unroll
        for (int np = 0; np < 2; ++np) {
            int n = wn * 32 + np * 16 + ((lm >> 1) << 3) + l8;
            boff[np] = (uint32_t)(n * HSTRIDE + ((lm & 1) << 3)) * 2u;
        }

        float acc[4][4][4];
#pragma unroll
        for (int mi = 0; mi < 4; ++mi)
#pragma unroll
            for (int ni = 0; ni < 4; ++ni)
#pragma unroll
                for (int q = 0; q < 4; ++q) acc[mi][ni][q] = 0.f;

        for (int kt = 0; kt < NKT; ++kt) {
            const int s = kt & 3;
            bar_sync(1 + s);                                // FULL[s]
            const uint32_t sA16 = sbase + (uint32_t)s * STAGE_BYTES;
            const uint32_t sB16 = sA16 + STAGE_A + STAGE_BF;

            // ---- LDSM burst: all fragments for both kk halves ----
            uint32_t a[2][4][4], bb[2][4][2];
#pragma unroll
            for (int kk = 0; kk < 2; ++kk) {
                const uint32_t kbyte = kk * 32;   // 16 halves
#pragma unroll
                for (int mi = 0; mi < 4; ++mi)
                    LDSM4(a[kk][mi][0], a[kk][mi][1], a[kk][mi][2],
                          a[kk][mi][3], sA16 + aoff[mi] + kbyte);
#pragma unroll
                for (int np = 0; np < 2; ++np)
                    LDSM4(bb[kk][np * 2][0], bb[kk][np * 2][1],
                          bb[kk][np * 2 + 1][0], bb[kk][np * 2 + 1][1],
                          sB16 + boff[np] + kbyte);
            }
            bar_arrive(5 + s);                              // FREE[s] early

            // ---- HMMA burst (registers only) ----
#pragma unroll
            for (int kk = 0; kk < 2; ++kk)
#pragma unroll
                for (int mi = 0; mi < 4; ++mi)
#pragma unroll
                    for (int ni = 0; ni < 4; ++ni)
                        asm volatile(
                            "mma.sync.aligned.m16n8k16.row.col.f32.f16.f16.f32 "
                            "{%0,%1,%2,%3}, {%4,%5,%6,%7}, {%8,%9}, {%0,%1,%2,%3};"
                            : "+f"(acc[mi][ni][0]), "+f"(acc[mi][ni][1]),
                              "+f"(acc[mi][ni][2]), "+f"(acc[mi][ni][3])
                            : "r"(a[kk][mi][0]), "r"(a[kk][mi][1]),
                              "r"(a[kk][mi][2]), "r"(a[kk][mi][3]),
                              "r"(bb[kk][ni][0]), "r"(bb[kk][ni][1]));
        }

        // write K-split partial
        const int gid = lane >> 2;
        const int tig = lane & 3;
        float* outp = g_C + (size_t)ks * MROWS * NBUS;
#pragma unroll
        for (int mi = 0; mi < 4; ++mi) {
            int r0 = wm * 64 + mi * 16 + gid;
#pragma unroll
            for (int ni = 0; ni < 4; ++ni) {
                int col = n0 + wn * 32 + ni * 8 + tig * 2;
                *(float2*)&outp[(size_t)r0 * NBUS + col] =
                    make_float2(acc[mi][ni][0], acc[mi][ni][1]);
                *(float2*)&outp[(size_t)(r0 + 8) * NBUS + col] =
                    make_float2(acc[mi][ni][2], acc[mi][ni][3]);
            }
        }
    }
}

// ---------------------------------------------------------------------------
// reduce K-split partials + power-flow epilogue; 2 elems/thread
// ---------------------------------------------------------------------------
__global__ void epilogue_kernel(const float* __restrict__ Vm,
                                const float* __restrict__ Pin,
                                const float* __restrict__ Qin,
                                float* __restrict__ out) {
    int idx = blockIdx.x * blockDim.x + threadIdx.x;   // over BATCH*NBUS/2
    if (idx >= BATCH * NBUS / 2) return;
    int e = idx * 2;
    int b = e >> 12;
    int i = e & (NBUS - 1);

    float2 U = make_float2(0.f, 0.f);
    float2 W = make_float2(0.f, 0.f);
#pragma unroll
    for (int ksp = 0; ksp < KSPLIT; ++ksp) {
        const float2 u = *(const float2*)&g_C[((size_t)(ksp * MROWS) + b) * NBUS + i];
        const float2 w = *(const float2*)&g_C[((size_t)(ksp * MROWS) + BATCH + b) * NBUS + i];
        U.x += u.x; U.y += u.y;
        W.x += w.x; W.y += w.y;
    }
    const float2 vm  = *(const float2*)&Vm[e];
    const float2 pin = *(const float2*)&Pin[e];
    const float2 qin = *(const float2*)&Qin[e];
    const float4 tr  = *(const float4*)&g_trig[e];   // cs0,sn0,cs1,sn1

    float2 rp, rq;
    rp.x = vm.x * (tr.x * U.x + tr.y * W.x) - pin.x;
    rq.x = vm.x * (tr.y * U.x - tr.x * W.x) - qin.x;
    rp.y = vm.y * (tr.z * U.y + tr.w * W.y) - pin.y;
    rq.y = vm.y * (tr.w * U.y - tr.z * W.y) - qin.y;

    *(float2*)&out[e]                = rp;
    *(float2*)&out[BATCH * NBUS + e] = rq;
}

// ---------------------------------------------------------------------------
extern "C" void kernel_launch(void* const* d_in, const int* in_sizes, int n_in,
                              void* d_out, int out_size) {
    const float* Vm  = (const float*)d_in[0];
    const float* Va  = (const float*)d_in[1];
    const float* Pin = (const float*)d_in[2];
    const float* Qin = (const float*)d_in[3];
    const float* Gm  = (const float*)d_in[4];
    const float* Bm  = (const float*)d_in[5];
    float* out = (float*)d_out;

    cudaFuncSetAttribute(gemm_kernel,
                         cudaFuncAttributeMaxDynamicSharedMemorySize, SMEM_TOTAL);

    prep_kernel<<<(BATCH * NBUS / 2 + 255) / 256, 256>>>(Vm, Va);
    gemm_kernel<<<dim3(NBUS / BN, KSPLIT), THREADS, SMEM_TOTAL>>>(Gm, Bm);
    epilogue_kernel<<<(BATCH * NBUS / 2 + 255) / 256, 256>>>(Vm, Pin, Qin, out);
}

// round 7
// speedup vs baseline: 1.9241x; 1.0423x over previous
#include <cuda_runtime.h>
#include <cuda_fp16.h>
#include <cstdint>

#define NBUS   4096
#define BATCH  64
#define MROWS  128        // 2*BATCH RHS rows
#define KDIM   8192       // 2*NBUS
#define BN     128
#define BK     32         // K per unit
#define NCTA   148        // persistent: one CTA per SM
#define NTILES 32         // N tiles
#define KUNITS 256        // K chunks over full KDIM
#define NUNITS (NTILES * KUNITS)   // 8192
#define NSTAGES 4
#define THREADS 384               // 8 consumer warps + 4 producer warps

#define HSTRIDE 40                 // halves per padded row (80 B, 20-bank stride)
#define STAGE_A   10240            // fp16 X tile 128 x 32 (padded rows)
#define STAGE_BF  16384            // fp32 B staging 128 x 32
#define STAGE_B16 10240            // fp16 B tile
#define STAGE_BYTES (STAGE_A + STAGE_BF + STAGE_B16)   // 36864
#define SMEM_TOTAL  (NSTAGES * STAGE_BYTES)            // 147456

// named barrier ids: FULL[s]=1+s, FREE[s]=5+s; count = all 384 threads
#define BAR_CNT 384

// Scratch (no runtime allocation allowed)
__device__ __half  g_X16[MROWS * KDIM];          // 2 MB stacked RHS (fp16)
__device__ float   g_C[MROWS * NBUS];            // 2 MB accumulators (atomic)
__device__ float2  g_trig[BATCH * NBUS];         // 2 MB cached (cos, sin)

// ---------------------------------------------------------------------------
// Kernel 1: build X (fp16), cache (cos,sin), zero g_C
// ---------------------------------------------------------------------------
__global__ void prep_kernel(const float* __restrict__ Vm,
                            const float* __restrict__ Va) {
    int t = blockIdx.x * blockDim.x + threadIdx.x;   // over BATCH*NBUS/2 = 131072
    if (t >= BATCH * NBUS / 2) return;
    // zero accumulators: 524288 floats / 131072 threads = 1 float4 each
    *(float4*)&g_C[t * 4] = make_float4(0.f, 0.f, 0.f, 0.f);

    int e = t * 2;
    int b = e >> 12;
    int j = e & (NBUS - 1);
    const float2 vm = *(const float2*)&Vm[e];
    const float2 va = *(const float2*)&Va[e];
    float sn0, cs0, sn1, cs1;
    __sincosf(va.x, &sn0, &cs0);
    __sincosf(va.y, &sn1, &cs1);
    __half2 hc = __floats2half2_rn(vm.x * cs0, vm.y * cs1);
    __half2 hs = __floats2half2_rn(vm.x * sn0, vm.y * sn1);
    __half2 hn = __hneg2(hc);
    *(uint32_t*)&g_X16[b * KDIM + j]                  = *(uint32_t*)&hc;
    *(uint32_t*)&g_X16[b * KDIM + NBUS + j]           = *(uint32_t*)&hs;
    *(uint32_t*)&g_X16[(BATCH + b) * KDIM + j]        = *(uint32_t*)&hs;
    *(uint32_t*)&g_X16[(BATCH + b) * KDIM + NBUS + j] = *(uint32_t*)&hn;
    *(float4*)&g_trig[e] = make_float4(cs0, sn0, cs1, sn1);
}

// ---------------------------------------------------------------------------
__device__ __forceinline__ void cp16(uint32_t saddr, const void* gptr) {
    asm volatile("cp.async.cg.shared.global [%0], [%1], 16;\n"
                 :: "r"(saddr), "l"(gptr));
}

__device__ __forceinline__ void bar_sync(int id) {
    asm volatile("bar.sync %0, %1;" :: "r"(id), "n"(BAR_CNT) : "memory");
}
__device__ __forceinline__ void bar_arrive(int id) {
    asm volatile("bar.arrive %0, %1;" :: "r"(id), "n"(BAR_CNT) : "memory");
}

#define LDSM4(r0, r1, r2, r3, addr)                                           \
    asm volatile("ldmatrix.sync.aligned.m8n8.x4.shared.b16 "                  \
                 "{%0,%1,%2,%3}, [%4];"                                       \
                 : "=r"(r0), "=r"(r1), "=r"(r2), "=r"(r3) : "r"(addr))

// ---------------------------------------------------------------------------
// Persistent warp-specialized fp16 GEMM over 8192 (n_tile, kt) units.
//   unit u: n_tile = u>>8 (BN=128 cols), kt = u&255 (BK=32 of KDIM=8192)
//   kt<128 -> G (X cols 0..4095), kt>=128 -> B (X cols 4096..8191)
//   CTA i handles units [i*8192/148, (i+1)*8192/148); flushes each n_tile
//   segment into g_C via atomicAdd.
// ---------------------------------------------------------------------------
__global__ void __launch_bounds__(THREADS)
gemm_kernel(const float* __restrict__ Gm, const float* __restrict__ Bm) {
    extern __shared__ char smem[];
    uint32_t sbase;
    asm("{ .reg .u64 t; cvta.to.shared.u64 t, %1; cvt.u32.u64 %0, t; }"
        : "=r"(sbase) : "l"(smem));

    const int tid  = threadIdx.x;
    const int lane = tid & 31;
    const int warp = tid >> 5;

    const int start = (int)(((long long)blockIdx.x * NUNITS) / NCTA);
    const int end   = (int)(((long long)(blockIdx.x + 1) * NUNITS) / NCTA);

    if (warp >= 8) {
        // ================= PRODUCER =================
        const int ptid = tid - 256;   // 0..127

        auto issue = [&](int u) {
            const int s  = u & (NSTAGES - 1);
            const int nt = u >> 8;
            const int kt = u & 255;
            const uint32_t sA  = sbase + (uint32_t)s * STAGE_BYTES;
            const uint32_t sBF = sA + STAGE_A;
            const int n0  = nt * BN;
            const int kbx = kt * BK;                       // X column
            const float* mat = (kt < 128) ? Gm : Bm;
            const int kbm = (kt & 127) * BK;               // G/B column
#pragma unroll
            for (int it = 0; it < 4; ++it) {   // 512 x 16B : A tile
                int v   = ptid + it * 128;
                int row = v >> 2;
                int c   = v & 3;
                cp16(sA + (uint32_t)(row * 80 + c * 16),
                     (const void*)&g_X16[(size_t)row * KDIM + kbx + c * 8]);
            }
#pragma unroll
            for (int it = 0; it < 8; ++it) {   // 1024 x 16B : B fp32 staging
                int v   = ptid + it * 128;
                int row = v >> 3;
                int c   = v & 7;
                cp16(sBF + (uint32_t)(row * 128 + c * 16),
                     (const void*)&mat[(size_t)(n0 + row) * NBUS + kbm + c * 4]);
            }
        };
        auto convert = [&](int u) {
            const int s = u & (NSTAGES - 1);
            const float* bf  = (const float*)(smem + s * STAGE_BYTES + STAGE_A);
            __half*      b16 = (__half*)(smem + s * STAGE_BYTES + STAGE_A + STAGE_BF);
#pragma unroll
            for (int p = 0; p < 8; ++p) {
                int e = (ptid + p * 128) * 4;
                float4 v = *(const float4*)(bf + e);
                int row = e >> 5, k = e & 31;
                __half2 h0 = __floats2half2_rn(v.x, v.y);
                __half2 h1 = __floats2half2_rn(v.z, v.w);
                uint2 pk;
                pk.x = *(uint32_t*)&h0;
                pk.y = *(uint32_t*)&h1;
                *(uint2*)(b16 + row * HSTRIDE + k) = pk;
            }
        };

        for (int u = start; u < end; ++u) {
            if (u - start >= NSTAGES) bar_sync(5 + (u & 3));   // FREE[s]
            issue(u);
            asm volatile("cp.async.commit_group;");
            if (u - start >= 2) {
                asm volatile("cp.async.wait_group 2;");
                convert(u - 2);
                bar_arrive(1 + ((u - 2) & 3));                 // FULL[s]
            }
        }
        asm volatile("cp.async.wait_group 0;");
        convert(end - 2);
        bar_arrive(1 + ((end - 2) & 3));
        convert(end - 1);
        bar_arrive(1 + ((end - 1) & 3));
    } else {
        // ================= CONSUMER =================
        const int wm = warp & 1;    // 2 M-warps * 64 rows
        const int wn = warp >> 1;   // 4 N-warps * 32 cols
        const int lm = lane >> 3;
        const int l8 = lane & 7;

        uint32_t aoff[4], boff[2];
#pragma unroll
        for (int mi = 0; mi < 4; ++mi) {
            int row = wm * 64 + mi * 16 + ((lm & 1) << 3) + l8;
            aoff[mi] = (uint32_t)(row * HSTRIDE + ((lm >> 1) << 3)) * 2u;
        }
#pragma unroll
        for (int np = 0; np < 2; ++np) {
            int n = wn * 32 + np * 16 + ((lm >> 1) << 3) + l8;
            boff[np] = (uint32_t)(n * HSTRIDE + ((lm & 1) << 3)) * 2u;
        }

        float acc[4][4][4];
#pragma unroll
        for (int mi = 0; mi < 4; ++mi)
#pragma unroll
            for (int ni = 0; ni < 4; ++ni)
#pragma unroll
                for (int q = 0; q < 4; ++q) acc[mi][ni][q] = 0.f;

        const int gid = lane >> 2;
        const int tig = lane & 3;

        auto flush = [&](int nt) {
            const int n0 = nt * BN;
#pragma unroll
            for (int mi = 0; mi < 4; ++mi) {
                int r0 = wm * 64 + mi * 16 + gid;
#pragma unroll
                for (int ni = 0; ni < 4; ++ni) {
                    int col = n0 + wn * 32 + ni * 8 + tig * 2;
                    atomicAdd(&g_C[(size_t)r0 * NBUS + col],       acc[mi][ni][0]);
                    atomicAdd(&g_C[(size_t)r0 * NBUS + col + 1],   acc[mi][ni][1]);
                    atomicAdd(&g_C[(size_t)(r0 + 8) * NBUS + col],     acc[mi][ni][2]);
                    atomicAdd(&g_C[(size_t)(r0 + 8) * NBUS + col + 1], acc[mi][ni][3]);
                    acc[mi][ni][0] = 0.f; acc[mi][ni][1] = 0.f;
                    acc[mi][ni][2] = 0.f; acc[mi][ni][3] = 0.f;
                }
            }
        };

        int cur_nt = start >> 8;
        for (int u = start; u < end; ++u) {
            const int s = u & 3;
            bar_sync(1 + s);                                // FULL[s]
            const uint32_t sA16 = sbase + (uint32_t)s * STAGE_BYTES;
            const uint32_t sB16 = sA16 + STAGE_A + STAGE_BF;

            uint32_t a[2][4][4], bb[2][4][2];
#pragma unroll
            for (int kk = 0; kk < 2; ++kk) {
                const uint32_t kbyte = kk * 32;   // 16 halves
#pragma unroll
                for (int mi = 0; mi < 4; ++mi)
                    LDSM4(a[kk][mi][0], a[kk][mi][1], a[kk][mi][2],
                          a[kk][mi][3], sA16 + aoff[mi] + kbyte);
#pragma unroll
                for (int np = 0; np < 2; ++np)
                    LDSM4(bb[kk][np * 2][0], bb[kk][np * 2][1],
                          bb[kk][np * 2 + 1][0], bb[kk][np * 2 + 1][1],
                          sB16 + boff[np] + kbyte);
            }
            bar_arrive(5 + s);                              // FREE[s]

#pragma unroll
            for (int kk = 0; kk < 2; ++kk)
#pragma unroll
                for (int mi = 0; mi < 4; ++mi)
#pragma unroll
                    for (int ni = 0; ni < 4; ++ni)
                        asm volatile(
                            "mma.sync.aligned.m16n8k16.row.col.f32.f16.f16.f32 "
                            "{%0,%1,%2,%3}, {%4,%5,%6,%7}, {%8,%9}, {%0,%1,%2,%3};"
                            : "+f"(acc[mi][ni][0]), "+f"(acc[mi][ni][1]),
                              "+f"(acc[mi][ni][2]), "+f"(acc[mi][ni][3])
                            : "r"(a[kk][mi][0]), "r"(a[kk][mi][1]),
                              "r"(a[kk][mi][2]), "r"(a[kk][mi][3]),
                              "r"(bb[kk][ni][0]), "r"(bb[kk][ni][1]));

            if (u == end - 1 || ((u + 1) >> 8) != cur_nt) {
                flush(cur_nt);
                cur_nt = (u + 1) >> 8;
            }
        }
    }
}

// ---------------------------------------------------------------------------
// power-flow epilogue; single accumulator buffer, 2 elems/thread
// ---------------------------------------------------------------------------
__global__ void epilogue_kernel(const float* __restrict__ Vm,
                                const float* __restrict__ Pin,
                                const float* __restrict__ Qin,
                                float* __restrict__ out) {
    int idx = blockIdx.x * blockDim.x + threadIdx.x;   // over BATCH*NBUS/2
    if (idx >= BATCH * NBUS / 2) return;
    int e = idx * 2;
    int b = e >> 12;
    int i = e & (NBUS - 1);

    const float2 U   = *(const float2*)&g_C[(size_t)b * NBUS + i];
    const float2 W   = *(const float2*)&g_C[(size_t)(BATCH + b) * NBUS + i];
    const float2 vm  = *(const float2*)&Vm[e];
    const float2 pin = *(const float2*)&Pin[e];
    const float2 qin = *(const float2*)&Qin[e];
    const float4 tr  = *(const float4*)&g_trig[e];   // cs0,sn0,cs1,sn1

    float2 rp, rq;
    rp.x = vm.x * (tr.x * U.x + tr.y * W.x) - pin.x;
    rq.x = vm.x * (tr.y * U.x - tr.x * W.x) - qin.x;
    rp.y = vm.y * (tr.z * U.y + tr.w * W.y) - pin.y;
    rq.y = vm.y * (tr.w * U.y - tr.z * W.y) - qin.y;

    *(float2*)&out[e]                = rp;
    *(float2*)&out[BATCH * NBUS + e] = rq;
}

// ---------------------------------------------------------------------------
extern "C" void kernel_launch(void* const* d_in, const int* in_sizes, int n_in,
                              void* d_out, int out_size) {
    const float* Vm  = (const float*)d_in[0];
    const float* Va  = (const float*)d_in[1];
    const float* Pin = (const float*)d_in[2];
    const float* Qin = (const float*)d_in[3];
    const float* Gm  = (const float*)d_in[4];
    const float* Bm  = (const float*)d_in[5];
    float* out = (float*)d_out;

    cudaFuncSetAttribute(gemm_kernel,
                         cudaFuncAttributeMaxDynamicSharedMemorySize, SMEM_TOTAL);

    prep_kernel<<<(BATCH * NBUS / 2 + 255) / 256, 256>>>(Vm, Va);
    gemm_kernel<<<NCTA, THREADS, SMEM_TOTAL>>>(Gm, Bm);
    epilogue_kernel<<<(BATCH * NBUS / 2 + 255) / 256, 256>>>(Vm, Pin, Qin, out);
}